// round 11
// baseline (speedup 1.0000x reference)
#include <cuda_runtime.h>
#include <cstdint>
#include <math.h>

// Problem constants
#define TPRIME 510
#define BATCH  32
#define CIN    128
#define TLEN   1024
#define FDIM   256
#define KCONV  640            // CIN * KW
#define HDIM   512
#define GDIM   2048           // 4*H
#define M_ROWS (TPRIME*BATCH) // 16320
#define NCTA_R 128            // persistent CTAs for recurrence

// recurrence smem layout: per-warp h slab = 32 b rows x 64 k
// row = [32 floats][8 shim][32 floats] -> halves at +0 / +40, stride 76
#define HROW   76
#define HSWARP (32*HROW)      // 2432 floats per warp slab
#define PSTR   20             // part: b stride
#define SKS    648            // part: ks stride (32*20 + 8 -> bank shift 8/ks)
#define TPAD   32             // tag padding (128B lines)

// ---------------- packed f32x2 helpers (Blackwell FFMA2 path) ----------------
__device__ __forceinline__ void ffma2(unsigned long long &d,
                                      unsigned long long a,
                                      unsigned long long b) {
    asm("fma.rn.f32x2 %0, %1, %2, %0;" : "+l"(d) : "l"(a), "l"(b));
}
__device__ __forceinline__ unsigned long long pk2(float x) {
    unsigned long long r;
    asm("mov.b64 %0, {%1, %1};" : "=l"(r) : "f"(x));
    return r;
}
__device__ __forceinline__ float2 upk(unsigned long long v) {
    float2 r;
    asm("mov.b64 {%0, %1}, %2;" : "=f"(r.x), "=f"(r.y) : "l"(v));
    return r;
}

// ---------------- scratch -----------------------------------------------------
__device__ float g_Wr[FDIM*KCONV];                    // conv_w transposed [f][k][c]
__device__ float g_feats[(size_t)M_ROWS*FDIM];        // conv output [m][F]
__device__ float g_xp[(size_t)M_ROWS*GDIM];           // x_proj [t*32+b][4H]
__device__ float g_hrec[2][NCTA_R*128];               // h records [parity][producer][b*4]
__device__ unsigned g_tag[2][NCTA_R*TPAD];            // producer tags, 128B apart
__device__ float g_pu[2][BATCH*NCTA_R];               // partial u-dot [b][cta]

// ---------------- prep --------------------------------------------------------
__global__ void prep_kernel(const float* __restrict__ conv_w)
{
    int stride = gridDim.x * blockDim.x;
    int i0 = blockIdx.x * blockDim.x + threadIdx.x;
    for (int i = i0; i < FDIM*KCONV; i += stride) {
        int f = i / KCONV;
        int rem = i - f*KCONV;
        int k = rem >> 7;
        int c = rem & 127;
        g_Wr[i] = conv_w[f*KCONV + c*5 + k];
    }
    for (int i = i0; i < NCTA_R*128; i += stride) g_hrec[0][i] = 0.f;
    for (int i = i0; i < NCTA_R*TPAD; i += stride) { g_tag[0][i] = 0u; g_tag[1][i] = 0u; }
}

// ---------------- conv as GEMM: [16320 x 640] * [640 x 256]^T -----------------
__global__ __launch_bounds__(256)
void conv_gemm(const float* __restrict__ x,
               const float* __restrict__ cb,
               const float* __restrict__ gam,
               const float* __restrict__ bet,
               const float* __restrict__ mu,
               const float* __restrict__ var)
{
    __shared__ float As[16][132];
    __shared__ float Bs[16][132];
    const int tid  = threadIdx.x;
    const int mblk = blockIdx.y * 128;
    const int nblk = blockIdx.x * 128;
    const int lrow = tid >> 1;
    const int lk   = (tid & 1) * 8;

    const int m = mblk + lrow;
    const bool mvalid = (m < M_ROWS);
    const float* arow = x;
    if (mvalid) {
        int t = m >> 5, b = m & 31;
        arow = x + (size_t)b * (TLEN*CIN) + (size_t)t * (2*CIN);
    }
    const float* brow = g_Wr + (size_t)(nblk + lrow) * KCONV;

    unsigned long long acc2[8][4];
#pragma unroll
    for (int i = 0; i < 8; i++)
#pragma unroll
        for (int j = 0; j < 4; j++) acc2[i][j] = 0ull;

    const int ty = tid >> 4, tx = tid & 15;

    for (int k0 = 0; k0 < KCONV; k0 += 16) {
        float4 a0 = make_float4(0.f,0.f,0.f,0.f), a1 = a0;
        if (mvalid) {
            a0 = *(const float4*)(arow + k0 + lk);
            a1 = *(const float4*)(arow + k0 + lk + 4);
        }
        float4 b0 = *(const float4*)(brow + k0 + lk);
        float4 b1 = *(const float4*)(brow + k0 + lk + 4);
        __syncthreads();
        As[lk+0][lrow]=a0.x; As[lk+1][lrow]=a0.y; As[lk+2][lrow]=a0.z; As[lk+3][lrow]=a0.w;
        As[lk+4][lrow]=a1.x; As[lk+5][lrow]=a1.y; As[lk+6][lrow]=a1.z; As[lk+7][lrow]=a1.w;
        Bs[lk+0][lrow]=b0.x; Bs[lk+1][lrow]=b0.y; Bs[lk+2][lrow]=b0.z; Bs[lk+3][lrow]=b0.w;
        Bs[lk+4][lrow]=b1.x; Bs[lk+5][lrow]=b1.y; Bs[lk+6][lrow]=b1.z; Bs[lk+7][lrow]=b1.w;
        __syncthreads();
#pragma unroll
        for (int k = 0; k < 16; k++) {
            float a[8];
            *(float4*)&a[0] = *(const float4*)&As[k][ty*4];
            *(float4*)&a[4] = *(const float4*)&As[k][ty*4+64];
            ulonglong2 bq0 = *(const ulonglong2*)&Bs[k][tx*4];
            ulonglong2 bq1 = *(const ulonglong2*)&Bs[k][tx*4+64];
#pragma unroll
            for (int i = 0; i < 8; i++) {
                unsigned long long aa = pk2(a[i]);
                ffma2(acc2[i][0], aa, bq0.x);
                ffma2(acc2[i][1], aa, bq0.y);
                ffma2(acc2[i][2], aa, bq1.x);
                ffma2(acc2[i][3], aa, bq1.y);
            }
        }
    }
#pragma unroll
    for (int j2 = 0; j2 < 4; j2++) {
        int nrel = (j2 < 2) ? (tx*4 + j2*2) : (64 + tx*4 + (j2-2)*2);
#pragma unroll
        for (int h = 0; h < 2; h++) {
            int n = nblk + nrel + h;
            float invv = gam[n] * rsqrtf(var[n] + 1e-5f);
            float addv = bet[n] - mu[n]*invv;
            float cbv  = cb[n];
#pragma unroll
            for (int i = 0; i < 8; i++) {
                int mm = mblk + ((i < 4) ? (ty*4 + i) : (64 + ty*4 + i - 4));
                if (mm < M_ROWS) {
                    float2 p = upk(acc2[i][j2]);
                    float v = ((h == 0) ? p.x : p.y) + cbv;
                    v = fmaxf(v, 0.f);
                    g_feats[(size_t)mm*FDIM + n] = v*invv + addv;
                }
            }
        }
    }
}

// ---------------- x_proj GEMM: [16320 x 256] * [256 x 2048]^T -----------------
__global__ __launch_bounds__(256)
void xproj_gemm(const float* __restrict__ w_ih,
                const float* __restrict__ b_ih,
                const float* __restrict__ b_hh)
{
    __shared__ float As[16][132];
    __shared__ float Bs[16][132];
    const int tid  = threadIdx.x;
    const int mblk = blockIdx.y * 128;
    const int nblk = blockIdx.x * 128;
    const int lrow = tid >> 1;
    const int lk   = (tid & 1) * 8;

    const int m = mblk + lrow;
    const bool mvalid = (m < M_ROWS);
    const float* arow = g_feats + (size_t)(mvalid ? m : 0) * FDIM;
    const float* brow = w_ih + (size_t)(nblk + lrow) * FDIM;

    unsigned long long acc2[8][4];
#pragma unroll
    for (int i = 0; i < 8; i++)
#pragma unroll
        for (int j = 0; j < 4; j++) acc2[i][j] = 0ull;

    const int ty = tid >> 4, tx = tid & 15;

    for (int k0 = 0; k0 < FDIM; k0 += 16) {
        float4 a0 = make_float4(0.f,0.f,0.f,0.f), a1 = a0;
        if (mvalid) {
            a0 = *(const float4*)(arow + k0 + lk);
            a1 = *(const float4*)(arow + k0 + lk + 4);
        }
        float4 b0 = *(const float4*)(brow + k0 + lk);
        float4 b1 = *(const float4*)(brow + k0 + lk + 4);
        __syncthreads();
        As[lk+0][lrow]=a0.x; As[lk+1][lrow]=a0.y; As[lk+2][lrow]=a0.z; As[lk+3][lrow]=a0.w;
        As[lk+4][lrow]=a1.x; As[lk+5][lrow]=a1.y; As[lk+6][lrow]=a1.z; As[lk+7][lrow]=a1.w;
        Bs[lk+0][lrow]=b0.x; Bs[lk+1][lrow]=b0.y; Bs[lk+2][lrow]=b0.z; Bs[lk+3][lrow]=b0.w;
        Bs[lk+4][lrow]=b1.x; Bs[lk+5][lrow]=b1.y; Bs[lk+6][lrow]=b1.z; Bs[lk+7][lrow]=b1.w;
        __syncthreads();
#pragma unroll
        for (int k = 0; k < 16; k++) {
            float a[8];
            *(float4*)&a[0] = *(const float4*)&As[k][ty*4];
            *(float4*)&a[4] = *(const float4*)&As[k][ty*4+64];
            ulonglong2 bq0 = *(const ulonglong2*)&Bs[k][tx*4];
            ulonglong2 bq1 = *(const ulonglong2*)&Bs[k][tx*4+64];
#pragma unroll
            for (int i = 0; i < 8; i++) {
                unsigned long long aa = pk2(a[i]);
                ffma2(acc2[i][0], aa, bq0.x);
                ffma2(acc2[i][1], aa, bq0.y);
                ffma2(acc2[i][2], aa, bq1.x);
                ffma2(acc2[i][3], aa, bq1.y);
            }
        }
    }
#pragma unroll
    for (int j2 = 0; j2 < 4; j2++) {
        int nrel = (j2 < 2) ? (tx*4 + j2*2) : (64 + tx*4 + (j2-2)*2);
#pragma unroll
        for (int h = 0; h < 2; h++) {
            int n = nblk + nrel + h;
            float bias = b_ih[n] + b_hh[n];
#pragma unroll
            for (int i = 0; i < 8; i++) {
                int mm = mblk + ((i < 4) ? (ty*4 + i) : (64 + ty*4 + i - 4));
                if (mm < M_ROWS) {
                    float2 p = upk(acc2[i][j2]);
                    g_xp[(size_t)mm*GDIM + n] = ((h == 0) ? p.x : p.y) + bias;
                }
            }
        }
    }
}

// ---------------- persistent skip-LSTM recurrence (pipelined, no barrier) -----
__device__ __forceinline__ float sigf(float v) {
    return __fdividef(1.f, 1.f + __expf(-v));
}
__device__ __forceinline__ float tanh_fast(float v) {
    float x = fminf(fmaxf(v, -15.f), 15.f);
    float e = __expf(2.f * x);
    return __fdividef(e - 1.f, e + 1.f);
}

__global__ __launch_bounds__(256)
void recur_kernel(const float* __restrict__ w_hh,
                  const float* __restrict__ w_uh,
                  const float* __restrict__ b_uh,
                  float* __restrict__ out)
{
    extern __shared__ float sm[];
    float* hs   = sm;                    // [8 warps][32 b][HROW]  h slabs (k = 64*warp..+64)
    float* part = hs + 8*HSWARP;         // [16 ks][32 b][PSTR]
    float* us   = part + 16*SKS;         // [32] u state

    const int tid  = threadIdx.x;
    const int warp = tid >> 5;
    const int lane = tid & 31;
    const int cta  = blockIdx.x;
    const int j0   = cta * 4;

    const int r  = tid & 15;             // row 0..15 (q = r>>2, jl = r&3)
    const int ks = tid >> 4;             // k-slice 0..15 (32 k each)

    // w_hh slice into registers: row (q*512 + j0 + jl), k in [ks*32, +32)
    ulonglong2 wreg[8];
    {
        int q = r >> 2, jl = r & 3;
        const float* wsrc = w_hh + (size_t)(q*HDIM + j0 + jl) * HDIM + ks*32;
#pragma unroll
        for (int i = 0; i < 8; i++)
            wreg[i] = *(const ulonglong2*)(wsrc + i*4);
    }
    if (tid < 32) us[tid] = 1.f;
    __syncthreads();

    const float wuh_l = (tid < 128) ? w_uh[j0 + (tid & 3)] : 0.f;
    const float buh   = b_uh[0];

    float c_reg = 0.f;                   // cell state for (b = tid>>2, jl = tid&3), tid<128
    float* hswp = hs + warp*HSWARP;

    for (int t = 0; t < TPRIME; t++) {
        const int p = t & 1;             // input buffer parity
        const int q = p ^ 1;             // output buffer parity

        // ---- xp gate values (independent of h; issue early) ------------------
        float xg[4];
        if (tid < 128) {
            int b = tid >> 2, jl = tid & 3;
            const float* xb = g_xp + ((size_t)t*BATCH + b)*GDIM + j0 + jl;
#pragma unroll
            for (int qq = 0; qq < 4; qq++) xg[qq] = __ldcg(xb + qq*HDIM);
        }

        // ---- staging: warp w waits on ITS 16 producers, then loads records ---
        {
            const unsigned tgt = (unsigned)t;
            const unsigned* myTag = &g_tag[p][(warp*16 + (lane & 15))*TPAD];
            bool ok;
            do {
                unsigned v = 0xFFFFFFFFu;
                if (lane < 16)
                    asm volatile("ld.acquire.gpu.global.u32 %0, [%1];"
                                 : "=r"(v) : "l"(myTag) : "memory");
                ok = (v >= tgt);
            } while (!__all_sync(0xffffffffu, ok));

            const float4* recs = (const float4*)&g_hrec[p][warp*16*128];
#pragma unroll
            for (int half = 0; half < 2; half++) {
                float4 hv[8];
#pragma unroll
                for (int j2 = 0; j2 < 8; j2++)
                    hv[j2] = __ldcg(recs + (half*8 + j2)*32 + lane);
#pragma unroll
                for (int j2 = 0; j2 < 8; j2++) {
                    int c = half*8 + j2;
                    int off = 4*c + ((c >> 3) << 3);   // halves at +0 / +40
                    *(float4*)&hswp[lane*HROW + off] = hv[j2];
                }
            }
            __syncwarp();
        }

        // ---- GEMM: acc[b] = dot(w[r][ks*32..+32], h[b][ks*32..+32]) ----------
        const float* hbase = hswp + (ks & 1)*40;
#pragma unroll 4
        for (int b4 = 0; b4 < 32; b4 += 4) {
            unsigned long long a0[4], a1[4];
#pragma unroll
            for (int bb = 0; bb < 4; bb++) { a0[bb] = 0ull; a1[bb] = 0ull; }
#pragma unroll
            for (int i = 0; i < 8; i++) {
#pragma unroll
                for (int bb = 0; bb < 4; bb++) {
                    ulonglong2 hq = *(const ulonglong2*)&hbase[(b4+bb)*HROW + i*4];
                    ffma2(a0[bb], wreg[i].x, hq.x);
                    ffma2(a1[bb], wreg[i].y, hq.y);
                }
            }
#pragma unroll
            for (int bb = 0; bb < 4; bb++) {
                float2 p0 = upk(a0[bb]), p1 = upk(a1[bb]);
                part[ks*SKS + (b4+bb)*PSTR + r] = (p0.x + p0.y) + (p1.x + p1.y);
            }
        }
        __syncthreads();

        // ---- reduce + u update + cell (tid<128: b=tid>>2, jl=tid&3) ----------
        if (tid < 128) {
            int b  = tid >> 2;
            int jl = tid & 3;

            // pu loads (previous step's partials; visibility via tag chain)
            float s_pu = 0.f;
            if (t > 0) {
                const float4* pp = (const float4*)&g_pu[(t-1)&1][b*NCTA_R + jl*32];
#pragma unroll
                for (int i = 0; i < 8; i++) {
                    float4 v = __ldcg(pp + i);
                    s_pu += v.x + v.y + v.z + v.w;
                }
            }

            float g4[4];
#pragma unroll
            for (int qq = 0; qq < 4; qq++) {
                float s = xg[qq];
                const float* pp2 = part + b*PSTR + qq*4 + jl;
#pragma unroll
                for (int k2 = 0; k2 < 16; k2++) s += pp2[k2*SKS];
                g4[qq] = s;
            }

            if (t > 0) {
                s_pu += __shfl_down_sync(0xffffffffu, s_pu, 1);
                s_pu += __shfl_down_sync(0xffffffffu, s_pu, 2);
                if (jl == 0) {
                    float du = sigf(s_pu + buh);
                    float u  = us[b];
                    float ub = rintf(u);
                    us[b] = ub*du + (1.f-ub)*(u + fminf(du, 1.f-u));
                }
            }
            __syncwarp();

            float u  = us[b];
            float ub = rintf(u);
            float ct = sigf(g4[1])*c_reg + sigf(g4[0])*tanh_fast(g4[2]);
            float ht = sigf(g4[3])*tanh_fast(ct);
            int hidx = j0 + jl;
            int hw = hidx >> 6;
            int ko = hidx & 63;
            int hoff = ko + ((ko >> 5) << 3);
            float hprev = hs[hw*HSWARP + b*HROW + hoff];
            float cn = ub*ct + (1.f-ub)*c_reg;
            float hn = ub*ht + (1.f-ub)*hprev;
            c_reg = cn;

            if (t == TPRIME-1) out[b*HDIM + j0 + jl] = hn;

            float h1  = __shfl_down_sync(0xffffffffu, hn, 1);
            float h2s = __shfl_down_sync(0xffffffffu, hn, 2);
            float h3  = __shfl_down_sync(0xffffffffu, hn, 3);
            float pv = cn * wuh_l;
            pv += __shfl_down_sync(0xffffffffu, pv, 1);
            pv += __shfl_down_sync(0xffffffffu, pv, 2);
            if (jl == 0 && t < TPRIME-1) {
                __stcg((float4*)&g_hrec[q][cta*128 + b*4], make_float4(hn, h1, h2s, h3));
                __stcg(&g_pu[p][b*NCTA_R + cta], pv);
            }
        }
        __syncthreads();   // record stores + slab/part reads complete block-wide

        // ---- release: tag = t+1 (visibility per grid.sync pattern) -----------
        if (t < TPRIME-1 && tid == 0) {
            asm volatile("st.release.gpu.global.u32 [%0], %1;"
                         :: "l"(&g_tag[q][cta*TPAD]), "r"((unsigned)(t+1)) : "memory");
        }
    }
}

// ---------------- launch -----------------------------------------------------
extern "C" void kernel_launch(void* const* d_in, const int* in_sizes, int n_in,
                              void* d_out, int out_size)
{
    const float* x      = (const float*)d_in[0];
    const float* conv_w = (const float*)d_in[1];
    const float* conv_b = (const float*)d_in[2];
    const float* gam    = (const float*)d_in[3];
    const float* bet    = (const float*)d_in[4];
    const float* mu     = (const float*)d_in[5];
    const float* var    = (const float*)d_in[6];
    const float* w_ih   = (const float*)d_in[7];
    const float* w_hh   = (const float*)d_in[8];
    const float* b_ih   = (const float*)d_in[9];
    const float* b_hh   = (const float*)d_in[10];
    const float* w_uh   = (const float*)d_in[11];
    const float* b_uh   = (const float*)d_in[12];

    const int smem_recur = (8*HSWARP + 16*SKS + 32) * (int)sizeof(float);
    cudaFuncSetAttribute(recur_kernel, cudaFuncAttributeMaxDynamicSharedMemorySize, smem_recur);

    prep_kernel<<<64, 256>>>(conv_w);
    conv_gemm<<<dim3(2, 128), 256>>>(x, conv_b, gam, bet, mu, var);
    xproj_gemm<<<dim3(16, 128), 256>>>(w_ih, b_ih, b_hh);
    recur_kernel<<<NCTA_R, 256, smem_recur>>>(w_hh, w_uh, b_uh, (float*)d_out);
}

// round 12
// speedup vs baseline: 1.2074x; 1.2074x over previous
#include <cuda_runtime.h>
#include <cstdint>
#include <math.h>

// Problem constants
#define TPRIME 510
#define BATCH  32
#define CIN    128
#define TLEN   1024
#define FDIM   256
#define KCONV  640            // CIN * KW
#define HDIM   512
#define GDIM   2048           // 4*H
#define M_ROWS (TPRIME*BATCH) // 16320
#define NCTA_R 128            // persistent CTAs for recurrence
#define WSTR   516            // padded smem row stride (floats) for GEMM kernels

// recurrence smem layout
// h slice row: 64 floats stored as [0..31][4-float shim][32..63] -> halves at +0 / +36
#define HSW    72             // h slice row stride (floats)
#define HSWARP (32*HSW)       // per-warp slice region
#define PSTR   20             // part: b stride
#define SKS    648            // part: ks stride (32*20 + 8 -> bank shift 8/ks)

// ---------------- packed f32x2 helpers (Blackwell FFMA2 path) ----------------
__device__ __forceinline__ void ffma2(unsigned long long &d,
                                      unsigned long long a,
                                      unsigned long long b) {
    asm("fma.rn.f32x2 %0, %1, %2, %0;" : "+l"(d) : "l"(a), "l"(b));
}
__device__ __forceinline__ unsigned long long pk2(float x) {
    unsigned long long r;
    asm("mov.b64 %0, {%1, %1};" : "=l"(r) : "f"(x));
    return r;
}
__device__ __forceinline__ float2 upk(unsigned long long v) {
    float2 r;
    asm("mov.b64 {%0, %1}, %2;" : "=f"(r.x), "=f"(r.y) : "l"(v));
    return r;
}

// ---------------- scratch -----------------------------------------------------
__device__ float g_Wr[FDIM*KCONV];                    // conv_w transposed [f][k][c]
__device__ float g_feats[(size_t)M_ROWS*FDIM];        // conv output [m][F]
__device__ float g_xp[(size_t)M_ROWS*GDIM];           // x_proj [t*32+b][4H]
__device__ float g_h[2][BATCH*HDIM];                  // double-buffered hidden state
__device__ float g_pu[2][BATCH*NCTA_R];               // partial u-dot [b][cta]
__device__ unsigned g_flags[NCTA_R*32];               // per-CTA step flags, 128B apart

// ---------------- prep --------------------------------------------------------
__global__ void prep_kernel(const float* __restrict__ conv_w)
{
    int stride = gridDim.x * blockDim.x;
    int i0 = blockIdx.x * blockDim.x + threadIdx.x;
    for (int i = i0; i < FDIM*KCONV; i += stride) {
        int f = i / KCONV;
        int rem = i - f*KCONV;
        int k = rem >> 7;
        int c = rem & 127;
        g_Wr[i] = conv_w[f*KCONV + c*5 + k];
    }
    for (int i = i0; i < BATCH*HDIM; i += stride) g_h[0][i] = 0.f;
    for (int i = i0; i < NCTA_R*32; i += stride) g_flags[i] = 0u;
}

// ---------------- conv as GEMM: [16320 x 640] * [640 x 256]^T -----------------
__global__ __launch_bounds__(256)
void conv_gemm(const float* __restrict__ x,
               const float* __restrict__ cb,
               const float* __restrict__ gam,
               const float* __restrict__ bet,
               const float* __restrict__ mu,
               const float* __restrict__ var)
{
    __shared__ float As[16][132];
    __shared__ float Bs[16][132];
    const int tid  = threadIdx.x;
    const int mblk = blockIdx.y * 128;
    const int nblk = blockIdx.x * 128;
    const int lrow = tid >> 1;
    const int lk   = (tid & 1) * 8;

    const int m = mblk + lrow;
    const bool mvalid = (m < M_ROWS);
    const float* arow = x;
    if (mvalid) {
        int t = m >> 5, b = m & 31;
        arow = x + (size_t)b * (TLEN*CIN) + (size_t)t * (2*CIN);
    }
    const float* brow = g_Wr + (size_t)(nblk + lrow) * KCONV;

    unsigned long long acc2[8][4];
#pragma unroll
    for (int i = 0; i < 8; i++)
#pragma unroll
        for (int j = 0; j < 4; j++) acc2[i][j] = 0ull;

    const int ty = tid >> 4, tx = tid & 15;

    for (int k0 = 0; k0 < KCONV; k0 += 16) {
        float4 a0 = make_float4(0.f,0.f,0.f,0.f), a1 = a0;
        if (mvalid) {
            a0 = *(const float4*)(arow + k0 + lk);
            a1 = *(const float4*)(arow + k0 + lk + 4);
        }
        float4 b0 = *(const float4*)(brow + k0 + lk);
        float4 b1 = *(const float4*)(brow + k0 + lk + 4);
        __syncthreads();
        As[lk+0][lrow]=a0.x; As[lk+1][lrow]=a0.y; As[lk+2][lrow]=a0.z; As[lk+3][lrow]=a0.w;
        As[lk+4][lrow]=a1.x; As[lk+5][lrow]=a1.y; As[lk+6][lrow]=a1.z; As[lk+7][lrow]=a1.w;
        Bs[lk+0][lrow]=b0.x; Bs[lk+1][lrow]=b0.y; Bs[lk+2][lrow]=b0.z; Bs[lk+3][lrow]=b0.w;
        Bs[lk+4][lrow]=b1.x; Bs[lk+5][lrow]=b1.y; Bs[lk+6][lrow]=b1.z; Bs[lk+7][lrow]=b1.w;
        __syncthreads();
#pragma unroll
        for (int k = 0; k < 16; k++) {
            float a[8];
            *(float4*)&a[0] = *(const float4*)&As[k][ty*4];
            *(float4*)&a[4] = *(const float4*)&As[k][ty*4+64];
            ulonglong2 bq0 = *(const ulonglong2*)&Bs[k][tx*4];
            ulonglong2 bq1 = *(const ulonglong2*)&Bs[k][tx*4+64];
#pragma unroll
            for (int i = 0; i < 8; i++) {
                unsigned long long aa = pk2(a[i]);
                ffma2(acc2[i][0], aa, bq0.x);
                ffma2(acc2[i][1], aa, bq0.y);
                ffma2(acc2[i][2], aa, bq1.x);
                ffma2(acc2[i][3], aa, bq1.y);
            }
        }
    }
#pragma unroll
    for (int j2 = 0; j2 < 4; j2++) {
        int nrel = (j2 < 2) ? (tx*4 + j2*2) : (64 + tx*4 + (j2-2)*2);
#pragma unroll
        for (int h = 0; h < 2; h++) {
            int n = nblk + nrel + h;
            float invv = gam[n] * rsqrtf(var[n] + 1e-5f);
            float addv = bet[n] - mu[n]*invv;
            float cbv  = cb[n];
#pragma unroll
            for (int i = 0; i < 8; i++) {
                int mm = mblk + ((i < 4) ? (ty*4 + i) : (64 + ty*4 + i - 4));
                if (mm < M_ROWS) {
                    float2 p = upk(acc2[i][j2]);
                    float v = ((h == 0) ? p.x : p.y) + cbv;
                    v = fmaxf(v, 0.f);
                    g_feats[(size_t)mm*FDIM + n] = v*invv + addv;
                }
            }
        }
    }
}

// ---------------- x_proj GEMM: [16320 x 256] * [256 x 2048]^T -----------------
__global__ __launch_bounds__(256)
void xproj_gemm(const float* __restrict__ w_ih,
                const float* __restrict__ b_ih,
                const float* __restrict__ b_hh)
{
    __shared__ float As[16][132];
    __shared__ float Bs[16][132];
    const int tid  = threadIdx.x;
    const int mblk = blockIdx.y * 128;
    const int nblk = blockIdx.x * 128;
    const int lrow = tid >> 1;
    const int lk   = (tid & 1) * 8;

    const int m = mblk + lrow;
    const bool mvalid = (m < M_ROWS);
    const float* arow = g_feats + (size_t)(mvalid ? m : 0) * FDIM;
    const float* brow = w_ih + (size_t)(nblk + lrow) * FDIM;

    unsigned long long acc2[8][4];
#pragma unroll
    for (int i = 0; i < 8; i++)
#pragma unroll
        for (int j = 0; j < 4; j++) acc2[i][j] = 0ull;

    const int ty = tid >> 4, tx = tid & 15;

    for (int k0 = 0; k0 < FDIM; k0 += 16) {
        float4 a0 = make_float4(0.f,0.f,0.f,0.f), a1 = a0;
        if (mvalid) {
            a0 = *(const float4*)(arow + k0 + lk);
            a1 = *(const float4*)(arow + k0 + lk + 4);
        }
        float4 b0 = *(const float4*)(brow + k0 + lk);
        float4 b1 = *(const float4*)(brow + k0 + lk + 4);
        __syncthreads();
        As[lk+0][lrow]=a0.x; As[lk+1][lrow]=a0.y; As[lk+2][lrow]=a0.z; As[lk+3][lrow]=a0.w;
        As[lk+4][lrow]=a1.x; As[lk+5][lrow]=a1.y; As[lk+6][lrow]=a1.z; As[lk+7][lrow]=a1.w;
        Bs[lk+0][lrow]=b0.x; Bs[lk+1][lrow]=b0.y; Bs[lk+2][lrow]=b0.z; Bs[lk+3][lrow]=b0.w;
        Bs[lk+4][lrow]=b1.x; Bs[lk+5][lrow]=b1.y; Bs[lk+6][lrow]=b1.z; Bs[lk+7][lrow]=b1.w;
        __syncthreads();
#pragma unroll
        for (int k = 0; k < 16; k++) {
            float a[8];
            *(float4*)&a[0] = *(const float4*)&As[k][ty*4];
            *(float4*)&a[4] = *(const float4*)&As[k][ty*4+64];
            ulonglong2 bq0 = *(const ulonglong2*)&Bs[k][tx*4];
            ulonglong2 bq1 = *(const ulonglong2*)&Bs[k][tx*4+64];
#pragma unroll
            for (int i = 0; i < 8; i++) {
                unsigned long long aa = pk2(a[i]);
                ffma2(acc2[i][0], aa, bq0.x);
                ffma2(acc2[i][1], aa, bq0.y);
                ffma2(acc2[i][2], aa, bq1.x);
                ffma2(acc2[i][3], aa, bq1.y);
            }
        }
    }
#pragma unroll
    for (int j2 = 0; j2 < 4; j2++) {
        int nrel = (j2 < 2) ? (tx*4 + j2*2) : (64 + tx*4 + (j2-2)*2);
#pragma unroll
        for (int h = 0; h < 2; h++) {
            int n = nblk + nrel + h;
            float bias = b_ih[n] + b_hh[n];
#pragma unroll
            for (int i = 0; i < 8; i++) {
                int mm = mblk + ((i < 4) ? (ty*4 + i) : (64 + ty*4 + i - 4));
                if (mm < M_ROWS) {
                    float2 p = upk(acc2[i][j2]);
                    g_xp[(size_t)mm*GDIM + n] = ((h == 0) ? p.x : p.y) + bias;
                }
            }
        }
    }
}

// ---------------- persistent skip-LSTM recurrence -----------------------------
__device__ __forceinline__ float sigf(float v) {
    return __fdividef(1.f, 1.f + __expf(-v));
}
__device__ __forceinline__ float tanh_fast(float v) {
    float x = fminf(fmaxf(v, -15.f), 15.f);
    float e = __expf(2.f * x);
    return __fdividef(e - 1.f, e + 1.f);
}

__global__ __launch_bounds__(256)
void recur_kernel(const float* __restrict__ w_hh,
                  const float* __restrict__ w_uh,
                  const float* __restrict__ b_uh,
                  float* __restrict__ out)
{
    extern __shared__ float sm[];
    float* hs   = sm;                    // [8 warps][32 b][HSW]   (slices of h, shimmed rows)
    float* part = hs + 8*HSWARP;         // [16 ks][32 b][PSTR]
    float* us   = part + 16*SKS;         // [32] u state

    const int tid  = threadIdx.x;
    const int warp = tid >> 5;
    const int lane = tid & 31;
    const int cta  = blockIdx.x;
    const int j0   = cta * 4;

    const int r  = tid & 15;             // row 0..15 (q = r>>2, jl = r&3)
    const int ks = tid >> 4;             // k-slice 0..15 (32 k each)

    // ---- w_hh slice into registers: row (q*512 + j0 + jl), k in [ks*32, +32)
    ulonglong2 wreg[8];
    {
        int q = r >> 2, jl = r & 3;
        const float* wsrc = w_hh + (size_t)(q*HDIM + j0 + jl) * HDIM + ks*32;
#pragma unroll
        for (int i = 0; i < 8; i++)
            wreg[i] = *(const ulonglong2*)(wsrc + i*4);
    }
    if (tid < 32) us[tid] = 1.f;
    __syncthreads();

    const float wuh_l = (tid < 128) ? w_uh[j0 + (tid & 3)] : 0.f;
    const float buh   = b_uh[0];

    float c_reg = 0.f;                   // cell state for (b = tid>>2, jl = tid&3), tid<128
    float* hswp = hs + warp*HSWARP;      // this warp's slice region

    for (int t = 0; t < TPRIME; t++) {
        const int ph = t & 1;

        // ---- load this warp's h slice: h[b][64*warp .. +64], 16 float4/lane ----
        const float4* hsrc = reinterpret_cast<const float4*>(g_h[ph]);
        float4 hv[16];
#pragma unroll
        for (int i = 0; i < 16; i++) {
            int f = i*32 + lane;                     // float4 index in slice
            int b = f >> 4, k4 = f & 15;
            hv[i] = __ldcg(hsrc + b*128 + warp*16 + k4);
        }

        // ---- xp gate values for cell update (tid<128: b=tid>>2, jl=tid&3) ----
        float xg[4];
        if (tid < 128) {
            int b = tid >> 2, jl = tid & 3;
            const float* xb = g_xp + ((size_t)t*BATCH + b)*GDIM + j0 + jl;
#pragma unroll
            for (int q = 0; q < 4; q++) xg[q] = __ldcg(xb + q*HDIM);
        }

        // ---- u update from previous step's partials (tid<128, 4 warps) -------
        if (t > 0 && tid < 128) {
            const float4* pp = (const float4*)&g_pu[(t-1)&1][(tid>>2)*NCTA_R + (tid&3)*32];
            float s = 0.f;
#pragma unroll
            for (int i = 0; i < 8; i++) {
                float4 v = __ldcg(pp + i);
                s += v.x + v.y + v.z + v.w;
            }
            s += __shfl_down_sync(0xffffffffu, s, 1);
            s += __shfl_down_sync(0xffffffffu, s, 2);
            if ((tid & 3) == 0) {
                int b = tid >> 2;
                float du = sigf(s + buh);
                float u  = us[b];
                float ub = rintf(u);
                us[b] = ub*du + (1.f-ub)*(u + fminf(du, 1.f-u));
            }
        }

        // ---- stage slice into smem (per-warp; shimmed row layout) ------------
#pragma unroll
        for (int i = 0; i < 16; i++) {
            int f = i*32 + lane;
            int b = f >> 4, k4 = f & 15;
            int off = k4*4 + ((k4 >> 3) << 2);       // halves at +0 / +36 floats
            *(float4*)&hswp[b*HSW + off] = hv[i];
        }
        __syncwarp();

        // ---- GEMM: acc[b] = dot(w[r][ks*32..+32], h[b][ks*32..+32]) ----------
        const float* hbase = hswp + (ks & 1)*36;
#pragma unroll 4
        for (int b4 = 0; b4 < 32; b4 += 4) {
            unsigned long long a0[4], a1[4];
#pragma unroll
            for (int bb = 0; bb < 4; bb++) { a0[bb] = 0ull; a1[bb] = 0ull; }
#pragma unroll
            for (int i = 0; i < 8; i++) {
#pragma unroll
                for (int bb = 0; bb < 4; bb++) {
                    ulonglong2 hq = *(const ulonglong2*)&hbase[(b4+bb)*HSW + i*4];
                    ffma2(a0[bb], wreg[i].x, hq.x);
                    ffma2(a1[bb], wreg[i].y, hq.y);
                }
            }
#pragma unroll
            for (int bb = 0; bb < 4; bb++) {
                float2 p0 = upk(a0[bb]), p1 = upk(a1[bb]);
                part[ks*SKS + (b4+bb)*PSTR + r] = (p0.x + p0.y) + (p1.x + p1.y);
            }
        }
        __syncthreads();

        // ---- fused k-reduce + cell update (tid<128: b=tid>>2, jl=tid&3) ------
        if (tid < 128) {
            int b  = tid >> 2;
            int jl = tid & 3;
            float g4[4];
#pragma unroll
            for (int q = 0; q < 4; q++) {
                float s = xg[q];
                const float* pp = part + b*PSTR + q*4 + jl;
#pragma unroll
                for (int k2 = 0; k2 < 16; k2++) s += pp[k2*SKS];
                g4[q] = s;
            }
            float u  = us[b];
            float ub = rintf(u);
            float ct = sigf(g4[1])*c_reg + sigf(g4[0])*tanh_fast(g4[2]);
            float ht = sigf(g4[3])*tanh_fast(ct);
            int hidx = j0 + jl;
            int hw = hidx >> 6;
            int ho = hidx & 63;
            int hoff = ho + ((ho >> 5) << 2);        // shimmed row offset
            float hprev = hs[hw*HSWARP + b*HSW + hoff];
            float cn = ub*ct + (1.f-ub)*c_reg;
            float hn = ub*ht + (1.f-ub)*hprev;
            c_reg = cn;

            __stcg(&g_h[ph^1][b*HDIM + j0 + jl], hn);
            if (t == TPRIME-1) out[b*HDIM + j0 + jl] = hn;

            float pv = cn * wuh_l;
            pv += __shfl_down_sync(0xffffffffu, pv, 1);
            pv += __shfl_down_sync(0xffffffffu, pv, 2);
            if (jl == 0) __stcg(&g_pu[ph][b*NCTA_R + cta], pv);
        }
        __syncthreads();

        // ---- distributed-flag grid barrier with paced polling ----------------
        if (t < TPRIME-1) {
            if (tid == 0) {
                asm volatile("st.release.gpu.global.u32 [%0], %1;"
                             :: "l"(&g_flags[cta*32]), "r"((unsigned)(t+1)) : "memory");
            }
            if (tid < NCTA_R) {
                const unsigned tgt = (unsigned)(t+1);
                unsigned v;
                asm volatile("ld.acquire.gpu.global.u32 %0, [%1];"
                             : "=r"(v) : "l"(&g_flags[tid*32]) : "memory");
                while (v < tgt) {
                    __nanosleep(40);                // throttle poll traffic
                    asm volatile("ld.acquire.gpu.global.u32 %0, [%1];"
                                 : "=r"(v) : "l"(&g_flags[tid*32]) : "memory");
                }
            }
            __syncthreads();
        }
    }
}

// ---------------- launch -----------------------------------------------------
extern "C" void kernel_launch(void* const* d_in, const int* in_sizes, int n_in,
                              void* d_out, int out_size)
{
    const float* x      = (const float*)d_in[0];
    const float* conv_w = (const float*)d_in[1];
    const float* conv_b = (const float*)d_in[2];
    const float* gam    = (const float*)d_in[3];
    const float* bet    = (const float*)d_in[4];
    const float* mu     = (const float*)d_in[5];
    const float* var    = (const float*)d_in[6];
    const float* w_ih   = (const float*)d_in[7];
    const float* w_hh   = (const float*)d_in[8];
    const float* b_ih   = (const float*)d_in[9];
    const float* b_hh   = (const float*)d_in[10];
    const float* w_uh   = (const float*)d_in[11];
    const float* b_uh   = (const float*)d_in[12];

    const int smem_recur = (8*HSWARP + 16*SKS + 32) * (int)sizeof(float);
    cudaFuncSetAttribute(recur_kernel, cudaFuncAttributeMaxDynamicSharedMemorySize, smem_recur);

    prep_kernel<<<64, 256>>>(conv_w);
    conv_gemm<<<dim3(2, 128), 256>>>(x, conv_b, gam, bet, mu, var);
    xproj_gemm<<<dim3(16, 128), 256>>>(w_ih, b_ih, b_hh);
    recur_kernel<<<NCTA_R, 256, smem_recur>>>(w_hh, w_uh, b_uh, (float*)d_out);
}

// round 13
// speedup vs baseline: 1.2130x; 1.0046x over previous
#include <cuda_runtime.h>
#include <cstdint>
#include <math.h>

// Problem constants
#define TPRIME 510
#define BATCH  32
#define CIN    128
#define TLEN   1024
#define FDIM   256
#define KCONV  640            // CIN * KW
#define HDIM   512
#define GDIM   2048           // 4*H
#define M_ROWS (TPRIME*BATCH) // 16320
#define NCTA_R 128            // persistent CTAs for recurrence
#define WSTR   516            // padded smem row stride (floats) for GEMM kernels

// recurrence smem layout
// h slice row: 64 floats stored as [0..31][4-float shim][32..63] -> halves at +0 / +36
#define HSW    72             // h slice row stride (floats)
#define HSWARP (32*HSW)       // per-warp slice region
#define PSTR   20             // part: b stride
#define SKS    648            // part: ks stride (32*20 + 8 -> bank shift 8/ks)

// ---------------- packed f32x2 helpers (Blackwell FFMA2 path) ----------------
__device__ __forceinline__ void ffma2(unsigned long long &d,
                                      unsigned long long a,
                                      unsigned long long b) {
    asm("fma.rn.f32x2 %0, %1, %2, %0;" : "+l"(d) : "l"(a), "l"(b));
}
__device__ __forceinline__ unsigned long long pk2(float x) {
    unsigned long long r;
    asm("mov.b64 %0, {%1, %1};" : "=l"(r) : "f"(x));
    return r;
}
__device__ __forceinline__ float2 upk(unsigned long long v) {
    float2 r;
    asm("mov.b64 {%0, %1}, %2;" : "=f"(r.x), "=f"(r.y) : "l"(v));
    return r;
}

// ---------------- scratch -----------------------------------------------------
__device__ float g_Wr[FDIM*KCONV];                    // conv_w transposed [f][k][c]
__device__ float g_feats[(size_t)M_ROWS*FDIM];        // conv output [m][F]
__device__ float g_h[2][BATCH*HDIM];                  // double-buffered hidden state
__device__ float g_pu[2][BATCH*NCTA_R];               // partial u-dot [b][cta]
__device__ unsigned g_flags[NCTA_R*32];               // per-CTA step flags, 128B apart

// ---------------- prep --------------------------------------------------------
__global__ void prep_kernel(const float* __restrict__ conv_w)
{
    int stride = gridDim.x * blockDim.x;
    int i0 = blockIdx.x * blockDim.x + threadIdx.x;
    for (int i = i0; i < FDIM*KCONV; i += stride) {
        int f = i / KCONV;
        int rem = i - f*KCONV;
        int k = rem >> 7;
        int c = rem & 127;
        g_Wr[i] = conv_w[f*KCONV + c*5 + k];
    }
    for (int i = i0; i < BATCH*HDIM; i += stride) g_h[0][i] = 0.f;
    for (int i = i0; i < NCTA_R*32; i += stride) g_flags[i] = 0u;
}

// ---------------- conv as GEMM: [16320 x 640] * [640 x 256]^T -----------------
__global__ __launch_bounds__(256)
void conv_gemm(const float* __restrict__ x,
               const float* __restrict__ cb,
               const float* __restrict__ gam,
               const float* __restrict__ bet,
               const float* __restrict__ mu,
               const float* __restrict__ var)
{
    __shared__ float As[16][132];
    __shared__ float Bs[16][132];
    const int tid  = threadIdx.x;
    const int mblk = blockIdx.y * 128;
    const int nblk = blockIdx.x * 128;
    const int lrow = tid >> 1;
    const int lk   = (tid & 1) * 8;

    const int m = mblk + lrow;
    const bool mvalid = (m < M_ROWS);
    const float* arow = x;
    if (mvalid) {
        int t = m >> 5, b = m & 31;
        arow = x + (size_t)b * (TLEN*CIN) + (size_t)t * (2*CIN);
    }
    const float* brow = g_Wr + (size_t)(nblk + lrow) * KCONV;

    unsigned long long acc2[8][4];
#pragma unroll
    for (int i = 0; i < 8; i++)
#pragma unroll
        for (int j = 0; j < 4; j++) acc2[i][j] = 0ull;

    const int ty = tid >> 4, tx = tid & 15;

    for (int k0 = 0; k0 < KCONV; k0 += 16) {
        float4 a0 = make_float4(0.f,0.f,0.f,0.f), a1 = a0;
        if (mvalid) {
            a0 = *(const float4*)(arow + k0 + lk);
            a1 = *(const float4*)(arow + k0 + lk + 4);
        }
        float4 b0 = *(const float4*)(brow + k0 + lk);
        float4 b1 = *(const float4*)(brow + k0 + lk + 4);
        __syncthreads();
        As[lk+0][lrow]=a0.x; As[lk+1][lrow]=a0.y; As[lk+2][lrow]=a0.z; As[lk+3][lrow]=a0.w;
        As[lk+4][lrow]=a1.x; As[lk+5][lrow]=a1.y; As[lk+6][lrow]=a1.z; As[lk+7][lrow]=a1.w;
        Bs[lk+0][lrow]=b0.x; Bs[lk+1][lrow]=b0.y; Bs[lk+2][lrow]=b0.z; Bs[lk+3][lrow]=b0.w;
        Bs[lk+4][lrow]=b1.x; Bs[lk+5][lrow]=b1.y; Bs[lk+6][lrow]=b1.z; Bs[lk+7][lrow]=b1.w;
        __syncthreads();
#pragma unroll
        for (int k = 0; k < 16; k++) {
            float a[8];
            *(float4*)&a[0] = *(const float4*)&As[k][ty*4];
            *(float4*)&a[4] = *(const float4*)&As[k][ty*4+64];
            ulonglong2 bq0 = *(const ulonglong2*)&Bs[k][tx*4];
            ulonglong2 bq1 = *(const ulonglong2*)&Bs[k][tx*4+64];
#pragma unroll
            for (int i = 0; i < 8; i++) {
                unsigned long long aa = pk2(a[i]);
                ffma2(acc2[i][0], aa, bq0.x);
                ffma2(acc2[i][1], aa, bq0.y);
                ffma2(acc2[i][2], aa, bq1.x);
                ffma2(acc2[i][3], aa, bq1.y);
            }
        }
    }
#pragma unroll
    for (int j2 = 0; j2 < 4; j2++) {
        int nrel = (j2 < 2) ? (tx*4 + j2*2) : (64 + tx*4 + (j2-2)*2);
#pragma unroll
        for (int h = 0; h < 2; h++) {
            int n = nblk + nrel + h;
            float invv = gam[n] * rsqrtf(var[n] + 1e-5f);
            float addv = bet[n] - mu[n]*invv;
            float cbv  = cb[n];
#pragma unroll
            for (int i = 0; i < 8; i++) {
                int mm = mblk + ((i < 4) ? (ty*4 + i) : (64 + ty*4 + i - 4));
                if (mm < M_ROWS) {
                    float2 p = upk(acc2[i][j2]);
                    float v = ((h == 0) ? p.x : p.y) + cbv;
                    v = fmaxf(v, 0.f);
                    g_feats[(size_t)mm*FDIM + n] = v*invv + addv;
                }
            }
        }
    }
}

// ---------------- persistent skip-LSTM recurrence (xproj fused in) ------------
__device__ __forceinline__ float sigf(float v) {
    return __fdividef(1.f, 1.f + __expf(-v));
}
__device__ __forceinline__ float tanh_fast(float v) {
    float x = fminf(fmaxf(v, -15.f), 15.f);
    float e = __expf(2.f * x);
    return __fdividef(e - 1.f, e + 1.f);
}

// xp tail: stage feats[tt] -> fts, dot with register-resident w_ih slices,
// reduce into per-thread xg[4] (tid<128). Caller provides syncs around phases.
__device__ __forceinline__ void xp_stage(float* fts, int tt, int tid)
{
    const float4* fsrc = reinterpret_cast<const float4*>(g_feats) + (size_t)tt * 2048;
#pragma unroll
    for (int i = 0; i < 8; i++) {
        int f = i*256 + tid;                 // float4 index: b = f>>6, k4 = f&63
        float4 v = __ldcg(fsrc + f);
        int b = f >> 6, k4 = f & 63;
        *(float4*)&fts[(k4 >> 2)*SKS + b*PSTR + (k4 & 3)*4] = v;
    }
}

__device__ __forceinline__ void xp_dot(const float* fts, float* part,
                                       const unsigned long long* wihreg,
                                       int r, int ks)
{
    const float* fb = fts + ks*SKS;
#pragma unroll 4
    for (int b = 0; b < 32; b++) {
        const float* fp = fb + b*PSTR;
        ulonglong2 f0 = *(const ulonglong2*)(fp);
        ulonglong2 f1 = *(const ulonglong2*)(fp + 4);
        ulonglong2 f2 = *(const ulonglong2*)(fp + 8);
        ulonglong2 f3 = *(const ulonglong2*)(fp + 12);
        unsigned long long a = 0ull;
        ffma2(a, wihreg[0], f0.x); ffma2(a, wihreg[1], f0.y);
        ffma2(a, wihreg[2], f1.x); ffma2(a, wihreg[3], f1.y);
        ffma2(a, wihreg[4], f2.x); ffma2(a, wihreg[5], f2.y);
        ffma2(a, wihreg[6], f3.x); ffma2(a, wihreg[7], f3.y);
        float2 p = upk(a);
        part[ks*SKS + b*PSTR + r] = p.x + p.y;
    }
}

__global__ __launch_bounds__(256)
void recur_kernel(const float* __restrict__ w_hh,
                  const float* __restrict__ w_ih,
                  const float* __restrict__ b_ih,
                  const float* __restrict__ b_hh,
                  const float* __restrict__ w_uh,
                  const float* __restrict__ b_uh,
                  float* __restrict__ out)
{
    extern __shared__ float sm[];
    float* hs   = sm;                    // [8 warps][32 b][HSW]   h slices (shimmed)
    float* part = hs + 8*HSWARP;         // [16 ks][32 b][PSTR]    (h-GEMM & xp partials)
    float* fts  = part + 16*SKS;         // [16 ks][32 b][PSTR]    feats tile
    float* us   = fts + 16*SKS;          // [32] u state

    const int tid  = threadIdx.x;
    const int warp = tid >> 5;
    const int lane = tid & 31;
    const int cta  = blockIdx.x;
    const int j0   = cta * 4;

    const int r  = tid & 15;             // row 0..15 (q = r>>2, jl = r&3)
    const int ks = tid >> 4;             // k-slice 0..15

    // ---- w_hh slice into registers: row (q*512 + j0 + jl), k in [ks*32, +32)
    ulonglong2 wreg[8];
    unsigned long long wihreg[8];        // w_ih row r slice: k in [ks*16, +16)
    {
        int q = r >> 2, jl = r & 3;
        const float* wsrc = w_hh + (size_t)(q*HDIM + j0 + jl) * HDIM + ks*32;
#pragma unroll
        for (int i = 0; i < 8; i++)
            wreg[i] = *(const ulonglong2*)(wsrc + i*4);
        const float* wsrc2 = w_ih + (size_t)(q*HDIM + j0 + jl) * FDIM + ks*16;
#pragma unroll
        for (int i = 0; i < 4; i++) {
            ulonglong2 v = *(const ulonglong2*)(wsrc2 + i*4);
            wihreg[2*i]   = v.x;
            wihreg[2*i+1] = v.y;
        }
    }
    if (tid < 32) us[tid] = 1.f;

    const float wuh_l = (tid < 128) ? w_uh[j0 + (tid & 3)] : 0.f;
    const float buh   = b_uh[0];

    // per-thread bias for the 4 gates of cell (b, j0+jl), tid<128
    float biasr[4];
    if (tid < 128) {
        int jl = tid & 3;
#pragma unroll
        for (int q = 0; q < 4; q++) {
            int row = q*HDIM + j0 + jl;
            biasr[q] = b_ih[row] + b_hh[row];
        }
    }
    __syncthreads();

    // ---- prologue: compute xg for t=0 ------------------------------------
    float xg[4] = {0.f, 0.f, 0.f, 0.f};
    {
        xp_stage(fts, 0, tid);
        __syncthreads();
        xp_dot(fts, part, wihreg, r, ks);
        __syncthreads();
        if (tid < 128) {
            int b = tid >> 2, jl = tid & 3;
#pragma unroll
            for (int q = 0; q < 4; q++) {
                float s = biasr[q];
                const float* pp = part + b*PSTR + q*4 + jl;
#pragma unroll
                for (int k2 = 0; k2 < 16; k2++) s += pp[k2*SKS];
                xg[q] = s;
            }
        }
        __syncthreads();   // part free for h-GEMM
    }

    float c_reg = 0.f;                   // cell state for (b = tid>>2, jl = tid&3)
    float* hswp = hs + warp*HSWARP;

    for (int t = 0; t < TPRIME; t++) {
        const int ph = t & 1;

        // ---- load this warp's h slice: h[b][64*warp .. +64] ------------------
        const float4* hsrc = reinterpret_cast<const float4*>(g_h[ph]);
        float4 hv[16];
#pragma unroll
        for (int i = 0; i < 16; i++) {
            int f = i*32 + lane;
            int b = f >> 4, k4 = f & 15;
            hv[i] = __ldcg(hsrc + b*128 + warp*16 + k4);
        }

        // ---- u update from previous step's partials (tid<128) ----------------
        if (t > 0 && tid < 128) {
            const float4* pp = (const float4*)&g_pu[(t-1)&1][(tid>>2)*NCTA_R + (tid&3)*32];
            float s = 0.f;
#pragma unroll
            for (int i = 0; i < 8; i++) {
                float4 v = __ldcg(pp + i);
                s += v.x + v.y + v.z + v.w;
            }
            s += __shfl_down_sync(0xffffffffu, s, 1);
            s += __shfl_down_sync(0xffffffffu, s, 2);
            if ((tid & 3) == 0) {
                int b = tid >> 2;
                float du = sigf(s + buh);
                float u  = us[b];
                float ub = rintf(u);
                us[b] = ub*du + (1.f-ub)*(u + fminf(du, 1.f-u));
            }
        }

        // ---- stage slice into smem (per-warp; shimmed rows) ------------------
#pragma unroll
        for (int i = 0; i < 16; i++) {
            int f = i*32 + lane;
            int b = f >> 4, k4 = f & 15;
            int off = k4*4 + ((k4 >> 3) << 2);       // halves at +0 / +36 floats
            *(float4*)&hswp[b*HSW + off] = hv[i];
        }
        __syncwarp();

        // ---- GEMM: acc[b] = dot(w[r][ks*32..+32], h[b][ks*32..+32]) ----------
        const float* hbase = hswp + (ks & 1)*36;
#pragma unroll 4
        for (int b4 = 0; b4 < 32; b4 += 4) {
            unsigned long long a0[4], a1[4];
#pragma unroll
            for (int bb = 0; bb < 4; bb++) { a0[bb] = 0ull; a1[bb] = 0ull; }
#pragma unroll
            for (int i = 0; i < 8; i++) {
#pragma unroll
                for (int bb = 0; bb < 4; bb++) {
                    ulonglong2 hq = *(const ulonglong2*)&hbase[(b4+bb)*HSW + i*4];
                    ffma2(a0[bb], wreg[i].x, hq.x);
                    ffma2(a1[bb], wreg[i].y, hq.y);
                }
            }
#pragma unroll
            for (int bb = 0; bb < 4; bb++) {
                float2 p0 = upk(a0[bb]), p1 = upk(a1[bb]);
                part[ks*SKS + (b4+bb)*PSTR + r] = (p0.x + p0.y) + (p1.x + p1.y);
            }
        }
        __syncthreads();

        // ---- fused k-reduce + cell update (tid<128: b=tid>>2, jl=tid&3) ------
        if (tid < 128) {
            int b  = tid >> 2;
            int jl = tid & 3;
            float g4[4];
#pragma unroll
            for (int q = 0; q < 4; q++) {
                float s = xg[q];
                const float* pp = part + b*PSTR + q*4 + jl;
#pragma unroll
                for (int k2 = 0; k2 < 16; k2++) s += pp[k2*SKS];
                g4[q] = s;
            }
            float u  = us[b];
            float ub = rintf(u);
            float ct = sigf(g4[1])*c_reg + sigf(g4[0])*tanh_fast(g4[2]);
            float ht = sigf(g4[3])*tanh_fast(ct);
            int hidx = j0 + jl;
            int hw = hidx >> 6;
            int ho = hidx & 63;
            int hoff = ho + ((ho >> 5) << 2);        // shimmed row offset
            float hprev = hs[hw*HSWARP + b*HSW + hoff];
            float cn = ub*ct + (1.f-ub)*c_reg;
            float hn = ub*ht + (1.f-ub)*hprev;
            c_reg = cn;

            __stcg(&g_h[ph^1][b*HDIM + j0 + jl], hn);
            if (t == TPRIME-1) out[b*HDIM + j0 + jl] = hn;

            float pv = cn * wuh_l;
            pv += __shfl_down_sync(0xffffffffu, pv, 1);
            pv += __shfl_down_sync(0xffffffffu, pv, 2);
            if (jl == 0) __stcg(&g_pu[ph][b*NCTA_R + cta], pv);
        }
        __syncthreads();

        if (t < TPRIME-1) {
            // ---- release flag FIRST (unblock peers) --------------------------
            if (tid == 0) {
                asm volatile("st.release.gpu.global.u32 [%0], %1;"
                             :: "l"(&g_flags[cta*32]), "r"((unsigned)(t+1)) : "memory");
            }

            // ---- xp for step t+1 in the barrier's shadow ---------------------
            xp_stage(fts, t+1, tid);
            __syncthreads();
            xp_dot(fts, part, wihreg, r, ks);
            __syncthreads();
            if (tid < 128) {
                int b = tid >> 2, jl = tid & 3;
#pragma unroll
                for (int q = 0; q < 4; q++) {
                    float s = biasr[q];
                    const float* pp = part + b*PSTR + q*4 + jl;
#pragma unroll
                    for (int k2 = 0; k2 < 16; k2++) s += pp[k2*SKS];
                    xg[q] = s;
                }
            }

            // ---- paced poll --------------------------------------------------
            if (tid < NCTA_R) {
                const unsigned tgt = (unsigned)(t+1);
                unsigned v;
                asm volatile("ld.acquire.gpu.global.u32 %0, [%1];"
                             : "=r"(v) : "l"(&g_flags[tid*32]) : "memory");
                while (v < tgt) {
                    __nanosleep(40);
                    asm volatile("ld.acquire.gpu.global.u32 %0, [%1];"
                                 : "=r"(v) : "l"(&g_flags[tid*32]) : "memory");
                }
            }
            __syncthreads();
        }
    }
}

// ---------------- launch -----------------------------------------------------
extern "C" void kernel_launch(void* const* d_in, const int* in_sizes, int n_in,
                              void* d_out, int out_size)
{
    const float* x      = (const float*)d_in[0];
    const float* conv_w = (const float*)d_in[1];
    const float* conv_b = (const float*)d_in[2];
    const float* gam    = (const float*)d_in[3];
    const float* bet    = (const float*)d_in[4];
    const float* mu     = (const float*)d_in[5];
    const float* var    = (const float*)d_in[6];
    const float* w_ih   = (const float*)d_in[7];
    const float* w_hh   = (const float*)d_in[8];
    const float* b_ih   = (const float*)d_in[9];
    const float* b_hh   = (const float*)d_in[10];
    const float* w_uh   = (const float*)d_in[11];
    const float* b_uh   = (const float*)d_in[12];

    const int smem_recur = (8*HSWARP + 16*SKS + 16*SKS + 32) * (int)sizeof(float);
    cudaFuncSetAttribute(recur_kernel, cudaFuncAttributeMaxDynamicSharedMemorySize, smem_recur);

    prep_kernel<<<64, 256>>>(conv_w);
    conv_gemm<<<dim3(2, 128), 256>>>(x, conv_b, gam, bet, mu, var);
    recur_kernel<<<NCTA_R, 256, smem_recur>>>(w_hh, w_ih, b_ih, b_hh, w_uh, b_uh,
                                              (float*)d_out);
}